// round 5
// baseline (speedup 1.0000x reference)
#include <cuda_runtime.h>
#include <cuda_bf16.h>
#include <cstdint>

// Problem constants
#define BATCH 64
#define TSTEPS 2048
#define DIN 128
#define HID 256
#define DOUT 128
#define G4H (4*HID)        // 1024

// Scan tiling: 16 column-groups x 8 batch-groups = 128 CTAs
#define NCTA 128
#define CLUSTER 16
#define JPC 16             // hidden units per CTA
#define NCOL 64            // gate columns per CTA
#define BPC 8              // batches per CTA
#define KTOT HID           // 256 (x projected upfront)
#define KC 32              // K per warp (8 warps)
#define NTHREADS 256

// padded SMEM strides (floats)
#define WSTR 260
#define HSTR 260
#define PSTR 68
#define XSTR 76

#define SM_W     0
#define SM_H     (SM_W + NCOL*WSTR)          // 16640
#define SM_PART  (SM_H + BPC*HSTR)           // +2080
#define SM_C     (SM_PART + 8*BPC*PSTR)      // +4352
#define SM_XP    (SM_C + JPC*BPC)            // +128
#define SM_HOUT  (SM_XP + BPC*XSTR)          // +608 ; mailbox 2 x 128 floats
#define SM_FLOATS (SM_HOUT + 2*JPC*BPC)
#define SMEM_BYTES (SM_FLOATS*4)             // ~96 KB

// x_proj kernel smem
#define XP_XSTRIDE 133
#define XP_WSTRIDE 132
#define XPK_SX    0
#define XPK_SW    (128*XP_XSTRIDE)
#define XPK_FLOATS (XPK_SW + 128*XP_WSTRIDE)
#define XPK_BYTES (XPK_FLOATS*4)

// Global scratch
__device__ __align__(16) float g_xp[(size_t)TSTEPS * 16 * 8 * 512]; // [t][cg][bg][bb*64+c]
__device__ __align__(16) float g_h[2][8][16][JPC*BPC];              // [buf][bg][cg][lj*8+bb]
__device__ unsigned g_flags[8][16][32];                             // fallback path

__device__ __forceinline__ uint32_t smem_u32(const void* p) {
    return (uint32_t)__cvta_generic_to_shared(p);
}
__device__ __forceinline__ uint32_t mapa_u32(uint32_t addr, uint32_t rank) {
    uint32_t r;
    asm("mapa.shared::cluster.u32 %0, %1, %2;" : "=r"(r) : "r"(addr), "r"(rank));
    return r;
}
__device__ __forceinline__ float fast_sig(float x) {
    return __fdividef(1.0f, 1.0f + __expf(-x));
}
__device__ __forceinline__ float fast_tanh(float x) {
    return __fdividef(2.0f, 1.0f + __expf(-2.0f * x)) - 1.0f;
}

// ---------------------------------------------------------------------------
__global__ void init_kernel() {
    int i = blockIdx.x * blockDim.x + threadIdx.x;
    if (i < 8 * 16 * 32) ((unsigned*)g_flags)[i] = 0u;
    if (i < 8 * 16 * JPC * BPC) ((float*)g_h[0])[i] = 0.0f;
}

// ---------------------------------------------------------------------------
// x_proj: g_xp[t][cg][bg][bb*64 + gate*16+lj] = x[b,t,:] . W_x[:, gcol] + bias
// ---------------------------------------------------------------------------
__global__ void __launch_bounds__(NTHREADS, 1)
xproj_kernel(const float* __restrict__ x,
             const float* __restrict__ W_x,
             const float* __restrict__ bias) {
    extern __shared__ float smem[];
    float* sX = smem + XPK_SX;
    float* sW = smem + XPK_SW;

    const int tid  = threadIdx.x;
    const int tblk = blockIdx.x;
    const int bg   = blockIdx.y;

    for (int idx = tid; idx < 128 * 32; idx += NTHREADS) {
        int r = idx >> 5, f4 = idx & 31;
        int tt = r >> 3, bb = r & 7;
        int b = bg * 8 + bb, t = tblk * 16 + tt;
        float4 v = __ldg(reinterpret_cast<const float4*>(
            x + ((size_t)b * TSTEPS + t) * DIN) + f4);
        float* dst = sX + r * XP_XSTRIDE + f4 * 4;
        dst[0] = v.x; dst[1] = v.y; dst[2] = v.z; dst[3] = v.w;
    }

    const int cq = tid & 7;
    const int rg = tid >> 3;

    for (int p = 0; p < 8; p++) {
        const int cp0 = p * 128;
        __syncthreads();
        for (int idx = tid; idx < 128 * 32; idx += NTHREADS) {
            int d = idx >> 5, c4 = idx & 31;
            float4 v = __ldg(reinterpret_cast<const float4*>(
                W_x + (size_t)d * G4H + cp0) + c4);
            float* dst = sW + d * XP_WSTRIDE + c4 * 4;
            dst[0] = v.x; dst[1] = v.y; dst[2] = v.z; dst[3] = v.w;
        }
        __syncthreads();

        unsigned long long acc[4][8];
        #pragma unroll
        for (int qq = 0; qq < 8; qq++) {
            float2 bv = __ldg(reinterpret_cast<const float2*>(
                bias + cp0 + 2 * (cq + 8 * qq)));
            unsigned long long bu;
            asm("mov.b64 %0, {%1, %2};" : "=l"(bu) : "f"(bv.x), "f"(bv.y));
            #pragma unroll
            for (int rr = 0; rr < 4; rr++) acc[rr][qq] = bu;
        }

        #pragma unroll 4
        for (int d = 0; d < 128; d++) {
            unsigned long long x2[4];
            #pragma unroll
            for (int rr = 0; rr < 4; rr++) {
                float xv = sX[(rg * 4 + rr) * XP_XSTRIDE + d];
                asm("mov.b64 %0, {%1, %1};" : "=l"(x2[rr]) : "f"(xv));
            }
            const uint32_t wrow = smem_u32(sW + d * XP_WSTRIDE + 2 * cq);
            #pragma unroll
            for (int qq = 0; qq < 8; qq++) {
                unsigned long long w2;
                asm volatile("ld.shared.u64 %0, [%1];"
                             : "=l"(w2) : "r"(wrow + qq * 64));
                #pragma unroll
                for (int rr = 0; rr < 4; rr++)
                    asm volatile("fma.rn.f32x2 %0, %1, %2, %0;"
                                 : "+l"(acc[rr][qq]) : "l"(x2[rr]), "l"(w2));
            }
        }

        #pragma unroll
        for (int rr = 0; rr < 4; rr++) {
            int r = rg * 4 + rr;
            int tt = r >> 3, bb = r & 7;
            int t = tblk * 16 + tt;
            #pragma unroll
            for (int qq = 0; qq < 8; qq++) {
                int cglob = cp0 + 2 * (cq + 8 * qq);
                int gate = cglob >> 8, rem = cglob & 255;
                int cg = rem >> 4, lj = rem & 15;
                float lo, hi;
                asm("mov.b64 {%0,%1}, %2;" : "=f"(lo), "=f"(hi) : "l"(acc[rr][qq]));
                float2* dst = reinterpret_cast<float2*>(
                    g_xp + ((size_t)((t * 16 + cg) * 8 + bg)) * 512
                         + bb * 64 + gate * 16 + lj);
                *dst = make_float2(lo, hi);
            }
        }
    }
}

// ===========================================================================
// Shared pieces of the scan body
// ===========================================================================
struct ScanCtx {
    float *sW, *sH, *sPart, *sC, *sXP;
    uint32_t haddr0, haddr1, waddr;
    int cq, bp, kc, k0, lane, tid;
};

__device__ __forceinline__ void scan_setup(ScanCtx& c, float* smem,
                                           const float* W_h, int cg) {
    c.sW = smem + SM_W;  c.sH = smem + SM_H;  c.sPart = smem + SM_PART;
    c.sC = smem + SM_C;  c.sXP = smem + SM_XP;
    c.tid = threadIdx.x;
    const int j0 = cg * JPC;
    for (int idx = c.tid; idx < NCOL * KTOT; idx += NTHREADS) {
        int k = idx >> 6, cc = idx & 63;
        int gate = cc >> 4, lj = cc & 15;
        c.sW[cc * WSTR + k] = W_h[(size_t)k * G4H + gate * HID + j0 + lj];
    }
    if (c.tid < JPC * BPC) c.sC[c.tid] = 0.0f;
    c.lane = c.tid & 31;
    c.cq = c.lane & 7;
    c.bp = c.lane >> 3;
    c.kc = c.tid >> 5;
    c.k0 = c.kc * KC;
    c.haddr0 = smem_u32(c.sH + (2 * c.bp) * HSTR + c.k0);
    c.haddr1 = smem_u32(c.sH + (2 * c.bp + 1) * HSTR + c.k0);
    c.waddr  = smem_u32(c.sW + c.cq * WSTR + c.k0);
}

// scatter one 512B h block (layout [lj*8+bb]) into sH[b][koff+lj]
__device__ __forceinline__ void scatter_h(float* sH, int koff, int lane,
                                          float4 a) {
    int e = 4 * lane;
    sH[((e + 0) & 7) * HSTR + koff + ((e + 0) >> 3)] = a.x;
    sH[((e + 1) & 7) * HSTR + koff + ((e + 1) >> 3)] = a.y;
    sH[((e + 2) & 7) * HSTR + koff + ((e + 2) >> 3)] = a.z;
    sH[((e + 3) & 7) * HSTR + koff + ((e + 3) >> 3)] = a.w;
}

__device__ __forceinline__ void scan_gemm(const ScanCtx& c,
                                          unsigned long long* a0,
                                          unsigned long long* a1) {
    #pragma unroll
    for (int q = 0; q < 8; q++) { a0[q] = 0ull; a1[q] = 0ull; }
    #pragma unroll
    for (int kk = 0; kk < KC; kk += 4) {
        unsigned long long h01a, h23a, h01b, h23b;
        asm volatile("ld.shared.v2.u64 {%0,%1}, [%2];"
                     : "=l"(h01a), "=l"(h23a) : "r"(c.haddr0 + kk * 4));
        asm volatile("ld.shared.v2.u64 {%0,%1}, [%2];"
                     : "=l"(h01b), "=l"(h23b) : "r"(c.haddr1 + kk * 4));
        #pragma unroll
        for (int q = 0; q < 8; q++) {
            unsigned long long w01, w23;
            asm volatile("ld.shared.v2.u64 {%0,%1}, [%2];"
                         : "=l"(w01), "=l"(w23)
                         : "r"(c.waddr + (q * (8 * WSTR) + kk) * 4));
            asm volatile("fma.rn.f32x2 %0, %1, %2, %0;"
                         : "+l"(a0[q]) : "l"(h01a), "l"(w01));
            asm volatile("fma.rn.f32x2 %0, %1, %2, %0;"
                         : "+l"(a0[q]) : "l"(h23a), "l"(w23));
            asm volatile("fma.rn.f32x2 %0, %1, %2, %0;"
                         : "+l"(a1[q]) : "l"(h01b), "l"(w01));
            asm volatile("fma.rn.f32x2 %0, %1, %2, %0;"
                         : "+l"(a1[q]) : "l"(h23b), "l"(w23));
        }
    }
}

__device__ __forceinline__ void scan_partials(const ScanCtx& c,
                                              const unsigned long long* a0,
                                              const unsigned long long* a1) {
    #pragma unroll
    for (int q = 0; q < 8; q++) {
        int cc = c.cq + 8 * q;
        float lo, hi;
        asm("mov.b64 {%0,%1}, %2;" : "=f"(lo), "=f"(hi) : "l"(a0[q]));
        c.sPart[(c.kc * BPC + 2 * c.bp) * PSTR + cc] = lo + hi;
        asm("mov.b64 {%0,%1}, %2;" : "=f"(lo), "=f"(hi) : "l"(a1[q]));
        c.sPart[(c.kc * BPC + 2 * c.bp + 1) * PSTR + cc] = lo + hi;
    }
}

// epilogue for thread tid<128; returns hnew
__device__ __forceinline__ float scan_epilogue(const ScanCtx& c) {
    int lj = c.tid >> 3;
    int bb = c.tid & 7;
    float g4[4];
    #pragma unroll
    for (int gate = 0; gate < 4; gate++) {
        int cc = gate * JPC + lj;
        float v = c.sXP[bb * XSTR + cc];
        #pragma unroll
        for (int q = 0; q < 8; q++)
            v += c.sPart[(q * BPC + bb) * PSTR + cc];
        g4[gate] = v;
    }
    float ig = fast_sig(g4[0]);
    float fg = fast_sig(g4[1]);
    float gg = fast_tanh(g4[2]);
    float og = fast_sig(g4[3]);
    float cnew = fg * c.sC[c.tid] + ig * gg;
    c.sC[c.tid] = cnew;
    return og * fast_tanh(cnew);
}

// ---------------------------------------------------------------------------
// CLUSTER variant: 16-CTA cluster per bg; DSMEM mailbox + barrier.cluster
// ---------------------------------------------------------------------------
__global__ void __launch_bounds__(NTHREADS, 1)
lstm_scan_cluster(const float* __restrict__ W_h) {
    extern __shared__ float smem[];
    float* sHout = smem + SM_HOUT;   // [buf][lj*8+bb]

    const int tid = threadIdx.x;
    uint32_t cg;
    asm("mov.u32 %0, %%cluster_ctarank;" : "=r"(cg));
    const int bg = blockIdx.x >> 4;

    ScanCtx c;
    scan_setup(c, smem, W_h, (int)cg);

    // zero mailbox (h_0 = 0)
    if (tid < 2 * JPC * BPC) sHout[tid] = 0.0f;
    __syncthreads();

    // peer mailbox base addresses for my two producers
    const uint32_t houtLocal = smem_u32(sHout);
    const uint32_t pA0 = mapa_u32(houtLocal, 2 * c.kc);
    const uint32_t pB0 = mapa_u32(houtLocal, 2 * c.kc + 1);

    // cluster phase 0: everyone's zeros visible
    asm volatile("barrier.cluster.arrive.aligned;" ::: "memory");
    asm volatile("barrier.cluster.wait.aligned;" ::: "memory");
    // pre-arrive for first loop wait
    asm volatile("barrier.cluster.arrive.aligned;" ::: "memory");

    for (int s = 0; s < TSTEPS; s++) {
        const int rbuf = s & 1;

        // prefetch x_proj slice while peers finish the previous step
        float2 xp = __ldg(reinterpret_cast<const float2*>(
            g_xp + ((size_t)((s * 16 + cg) * 8 + bg)) * 512) + tid);

        asm volatile("barrier.cluster.wait.aligned;" ::: "memory");

        // pull my two producer blocks from peer SMEM, scatter into sH
        {
            uint32_t aA = pA0 + rbuf * 512 + c.lane * 16;
            uint32_t aB = pB0 + rbuf * 512 + c.lane * 16;
            uint32_t r0, r1, r2, r3, t0, t1, t2, t3;
            asm volatile("ld.shared::cluster.v4.b32 {%0,%1,%2,%3}, [%4];"
                         : "=r"(r0), "=r"(r1), "=r"(r2), "=r"(r3) : "r"(aA));
            asm volatile("ld.shared::cluster.v4.b32 {%0,%1,%2,%3}, [%4];"
                         : "=r"(t0), "=r"(t1), "=r"(t2), "=r"(t3) : "r"(aB));
            scatter_h(c.sH, c.k0, c.lane,
                      make_float4(__uint_as_float(r0), __uint_as_float(r1),
                                  __uint_as_float(r2), __uint_as_float(r3)));
            scatter_h(c.sH, c.k0 + 16, c.lane,
                      make_float4(__uint_as_float(t0), __uint_as_float(t1),
                                  __uint_as_float(t2), __uint_as_float(t3)));
        }
        // stash xp for epilogue
        {
            int i0 = tid * 2;
            float* dst = c.sXP + (i0 >> 6) * XSTR + (i0 & 63);
            dst[0] = xp.x; dst[1] = xp.y;
        }
        __syncwarp();

        unsigned long long a0[8], a1[8];
        scan_gemm(c, a0, a1);
        scan_partials(c, a0, a1);
        __syncthreads();

        if (tid < JPC * BPC) {
            float hnew = scan_epilogue(c);
            sHout[((s + 1) & 1) * (JPC * BPC) + tid] = hnew;
        }
        // release the mailbox write to the cluster
        asm volatile("barrier.cluster.arrive.aligned;" ::: "memory");
    }
    asm volatile("barrier.cluster.wait.aligned;" ::: "memory");

    // final h (h_2048) sits in sHout buf 0 -> publish for fc
    __syncthreads();
    if (tid < JPC * BPC)
        g_h[0][bg][cg][tid] = sHout[tid];
}

// ---------------------------------------------------------------------------
// FALLBACK variant: global flags (proven R4 path)
// ---------------------------------------------------------------------------
__global__ void __launch_bounds__(NTHREADS, 1)
lstm_scan_flags(const float* __restrict__ W_h) {
    extern __shared__ float smem[];
    const int tid = threadIdx.x;
    const int cg  = blockIdx.x & 15;
    const int bg  = blockIdx.x >> 4;

    ScanCtx c;
    scan_setup(c, smem, W_h, cg);
    __syncthreads();

    unsigned* myflag = &g_flags[bg][cg][0];

    for (int s = 0; s < TSTEPS; s++) {
        const int rbuf = s & 1;
        float2 xp = __ldg(reinterpret_cast<const float2*>(
            g_xp + ((size_t)((s * 16 + cg) * 8 + bg)) * 512) + tid);

        if (s > 0) {
            if (c.lane < 2) {
                unsigned* f = &g_flags[bg][2 * c.kc + c.lane][0];
                unsigned v;
                do {
                    asm volatile("ld.acquire.gpu.global.u32 %0, [%1];"
                                 : "=r"(v) : "l"(f) : "memory");
                } while (v < (unsigned)s);
            }
            __syncwarp();
        }
        {
            const float4* pA = reinterpret_cast<const float4*>(g_h[rbuf][bg][2 * c.kc]);
            const float4* pB = reinterpret_cast<const float4*>(g_h[rbuf][bg][2 * c.kc + 1]);
            scatter_h(c.sH, c.k0, c.lane, __ldcg(pA + c.lane));
            scatter_h(c.sH, c.k0 + 16, c.lane, __ldcg(pB + c.lane));
        }
        {
            int i0 = tid * 2;
            float* dst = c.sXP + (i0 >> 6) * XSTR + (i0 & 63);
            dst[0] = xp.x; dst[1] = xp.y;
        }
        __syncwarp();

        unsigned long long a0[8], a1[8];
        scan_gemm(c, a0, a1);
        scan_partials(c, a0, a1);
        __syncthreads();

        if (tid < JPC * BPC) {
            float hnew = scan_epilogue(c);
            __stcg(&g_h[rbuf ^ 1][bg][cg][tid], hnew);
        }
        __syncthreads();

        if (tid == 0) {
            asm volatile("st.release.gpu.global.u32 [%0], %1;"
                         :: "l"(myflag), "r"((unsigned)(s + 1)) : "memory");
        }
    }
}

// ---------------------------------------------------------------------------
__global__ void fc_kernel(const float* __restrict__ fc_w,
                          const float* __restrict__ fc_b,
                          float* __restrict__ out) {
    int b = blockIdx.x;
    int d = threadIdx.x;
    int bg = b >> 3, bb = b & 7;
    float acc = fc_b[d];
    #pragma unroll 8
    for (int k = 0; k < HID; k++)
        acc += g_h[0][bg][k >> 4][(k & 15) * 8 + bb] * fc_w[k * DOUT + d];
    out[b * DOUT + d] = acc;
}

// ---------------------------------------------------------------------------
extern "C" void kernel_launch(void* const* d_in, const int* in_sizes, int n_in,
                              void* d_out, int out_size) {
    const float* x    = (const float*)d_in[0];
    const float* W_x  = (const float*)d_in[1];
    const float* W_h  = (const float*)d_in[2];
    const float* bvec = (const float*)d_in[3];
    const float* fc_w = (const float*)d_in[4];
    const float* fc_b = (const float*)d_in[5];
    float* out = (float*)d_out;

    cudaFuncSetAttribute(xproj_kernel,
                         cudaFuncAttributeMaxDynamicSharedMemorySize, XPK_BYTES);
    cudaFuncSetAttribute(lstm_scan_flags,
                         cudaFuncAttributeMaxDynamicSharedMemorySize, SMEM_BYTES);

    init_kernel<<<(8 * 16 * 128 + 255) / 256, 256>>>();
    xproj_kernel<<<dim3(TSTEPS / 16, 8), NTHREADS, XPK_BYTES>>>(x, W_x, bvec);

    // try the 16-CTA-cluster scan; fall back to flag-based scan
    bool cluster_ok = false;
    do {
        if (cudaFuncSetAttribute(lstm_scan_cluster,
                cudaFuncAttributeMaxDynamicSharedMemorySize, SMEM_BYTES)
            != cudaSuccess) break;
        if (cudaFuncSetAttribute(lstm_scan_cluster,
                cudaFuncAttributeNonPortableClusterSizeAllowed, 1)
            != cudaSuccess) break;

        cudaLaunchConfig_t cfg = {};
        cfg.gridDim = dim3(NCTA, 1, 1);
        cfg.blockDim = dim3(NTHREADS, 1, 1);
        cfg.dynamicSmemBytes = SMEM_BYTES;
        cudaLaunchAttribute attrs[1];
        attrs[0].id = cudaLaunchAttributeClusterDimension;
        attrs[0].val.clusterDim = {CLUSTER, 1, 1};
        cfg.attrs = attrs;
        cfg.numAttrs = 1;

        int nclusters = 0;
        if (cudaOccupancyMaxActiveClusters(&nclusters, lstm_scan_cluster, &cfg)
            != cudaSuccess) break;
        if (nclusters < NCTA / CLUSTER) break;   // must be fully co-resident

        if (cudaLaunchKernelEx(&cfg, lstm_scan_cluster, W_h) != cudaSuccess)
            break;
        cluster_ok = true;
    } while (0);

    if (!cluster_ok) {
        cudaGetLastError();  // clear any sticky error from the attempt
        lstm_scan_flags<<<NCTA, NTHREADS, SMEM_BYTES>>>(W_h);
    }

    fc_kernel<<<BATCH, DOUT>>>(fc_w, fc_b, out);
}

// round 6
// speedup vs baseline: 1.3666x; 1.3666x over previous
#include <cuda_runtime.h>
#include <cuda_bf16.h>
#include <cstdint>

// Problem constants
#define BATCH 64
#define TSTEPS 2048
#define DIN 128
#define HID 256
#define DOUT 128
#define G4H (4*HID)        // 1024

// Scan tiling: 16 column-groups x 8 batch-groups = 128 CTAs
#define NCTA 128
#define JPC 16             // hidden units per CTA
#define NCOL 64            // gate columns per CTA
#define BPC 8              // batches per CTA
#define KC 32              // K per warp (8 warps)
#define NTHREADS 256

// SMEM (floats)
#define SWSTR 66                         // sW2 [k][c] staging stride
#define PSTR 70                          // sPart row stride
#define SM_SW2   0                       // 256*66 = 16896 (setup only)
#define SM_H     (SM_SW2 + 256*SWSTR)    // sH [k(256)][b(8)] = 2048
#define SM_PART  (SM_H + 256*8)          // 2 x 8 x 8 x PSTR = 8960
#define SM_C     (SM_PART + 2*8*8*PSTR)  // 128
#define SM_FLOATS (SM_C + 128)
#define SMEM_BYTES (SM_FLOATS*4)         // ~113 KB

// x_proj kernel smem
#define XP_XSTRIDE 133
#define XP_WSTRIDE 132
#define XPK_SX    0
#define XPK_SW    (128*XP_XSTRIDE)
#define XPK_FLOATS (XPK_SW + 128*XP_WSTRIDE)
#define XPK_BYTES (XPK_FLOATS*4)

// Global scratch
__device__ __align__(16) float g_xp[(size_t)TSTEPS * 16 * 8 * 512]; // [t][cg][bg][bb*64+c]
__device__ __align__(16) float g_h[2][8][16][JPC*BPC];              // [buf][bg][cg][lj*8+bb]
__device__ unsigned g_flags[8][16][32];                             // [bg][cg], 128B apart

__device__ __forceinline__ uint32_t smem_u32(const void* p) {
    return (uint32_t)__cvta_generic_to_shared(p);
}
__device__ __forceinline__ float fast_sig(float x) {
    return __fdividef(1.0f, 1.0f + __expf(-x));
}
__device__ __forceinline__ float fast_tanh(float x) {
    return __fdividef(2.0f, 1.0f + __expf(-2.0f * x)) - 1.0f;
}

// ---------------------------------------------------------------------------
__global__ void init_kernel() {
    int i = blockIdx.x * blockDim.x + threadIdx.x;
    if (i < 8 * 16 * 32) ((unsigned*)g_flags)[i] = 0u;
    if (i < 8 * 16 * JPC * BPC) ((float*)g_h[0])[i] = 0.0f;
}

// ---------------------------------------------------------------------------
// x_proj: g_xp[t][cg][bg][bb*64 + gate*16+lj] = x[b,t,:] . W_x[:, gcol] + bias
// ---------------------------------------------------------------------------
__global__ void __launch_bounds__(NTHREADS, 1)
xproj_kernel(const float* __restrict__ x,
             const float* __restrict__ W_x,
             const float* __restrict__ bias) {
    extern __shared__ float smem[];
    float* sX = smem + XPK_SX;
    float* sW = smem + XPK_SW;

    const int tid  = threadIdx.x;
    const int tblk = blockIdx.x;
    const int bg   = blockIdx.y;

    for (int idx = tid; idx < 128 * 32; idx += NTHREADS) {
        int r = idx >> 5, f4 = idx & 31;
        int tt = r >> 3, bb = r & 7;
        int b = bg * 8 + bb, t = tblk * 16 + tt;
        float4 v = __ldg(reinterpret_cast<const float4*>(
            x + ((size_t)b * TSTEPS + t) * DIN) + f4);
        float* dst = sX + r * XP_XSTRIDE + f4 * 4;
        dst[0] = v.x; dst[1] = v.y; dst[2] = v.z; dst[3] = v.w;
    }

    const int cq = tid & 7;
    const int rg = tid >> 3;

    for (int p = 0; p < 8; p++) {
        const int cp0 = p * 128;
        __syncthreads();
        for (int idx = tid; idx < 128 * 32; idx += NTHREADS) {
            int d = idx >> 5, c4 = idx & 31;
            float4 v = __ldg(reinterpret_cast<const float4*>(
                W_x + (size_t)d * G4H + cp0) + c4);
            float* dst = sW + d * XP_WSTRIDE + c4 * 4;
            dst[0] = v.x; dst[1] = v.y; dst[2] = v.z; dst[3] = v.w;
        }
        __syncthreads();

        unsigned long long acc[4][8];
        #pragma unroll
        for (int qq = 0; qq < 8; qq++) {
            float2 bv = __ldg(reinterpret_cast<const float2*>(
                bias + cp0 + 2 * (cq + 8 * qq)));
            unsigned long long bu;
            asm("mov.b64 %0, {%1, %2};" : "=l"(bu) : "f"(bv.x), "f"(bv.y));
            #pragma unroll
            for (int rr = 0; rr < 4; rr++) acc[rr][qq] = bu;
        }

        #pragma unroll 4
        for (int d = 0; d < 128; d++) {
            unsigned long long x2[4];
            #pragma unroll
            for (int rr = 0; rr < 4; rr++) {
                float xv = sX[(rg * 4 + rr) * XP_XSTRIDE + d];
                asm("mov.b64 %0, {%1, %1};" : "=l"(x2[rr]) : "f"(xv));
            }
            const uint32_t wrow = smem_u32(sW + d * XP_WSTRIDE + 2 * cq);
            #pragma unroll
            for (int qq = 0; qq < 8; qq++) {
                unsigned long long w2;
                asm volatile("ld.shared.u64 %0, [%1];"
                             : "=l"(w2) : "r"(wrow + qq * 64));
                #pragma unroll
                for (int rr = 0; rr < 4; rr++)
                    asm volatile("fma.rn.f32x2 %0, %1, %2, %0;"
                                 : "+l"(acc[rr][qq]) : "l"(x2[rr]), "l"(w2));
            }
        }

        #pragma unroll
        for (int rr = 0; rr < 4; rr++) {
            int r = rg * 4 + rr;
            int tt = r >> 3, bb = r & 7;
            int t = tblk * 16 + tt;
            #pragma unroll
            for (int qq = 0; qq < 8; qq++) {
                int cglob = cp0 + 2 * (cq + 8 * qq);
                int gate = cglob >> 8, rem = cglob & 255;
                int cg = rem >> 4, lj = rem & 15;
                float lo, hi;
                asm("mov.b64 {%0,%1}, %2;" : "=f"(lo), "=f"(hi) : "l"(acc[rr][qq]));
                float2* dst = reinterpret_cast<float2*>(
                    g_xp + ((size_t)((t * 16 + cg) * 8 + bg)) * 512
                         + bb * 64 + gate * 16 + lj);
                *dst = make_float2(lo, hi);
            }
        }
    }
}

// ---------------------------------------------------------------------------
// persistent LSTM scan: W_h resident in REGISTERS, per-warp flag sync
// ---------------------------------------------------------------------------
__global__ void __launch_bounds__(NTHREADS, 1)
lstm_scan_kernel(const float* __restrict__ W_h) {
    extern __shared__ float smem[];
    float* sW2   = smem + SM_SW2;   // [k][c] staging (setup only)
    float* sH    = smem + SM_H;     // [k(256)][b(8)]
    float* sPart = smem + SM_PART;  // [buf][w][b][c] stride PSTR
    float* sC    = smem + SM_C;     // [lj*8+bb]

    const int tid = threadIdx.x;
    const int cg  = blockIdx.x & 15;
    const int bg  = blockIdx.x >> 4;
    const int j0  = cg * JPC;

    // ---- stage W_h slice as [k][c] then load into registers
    for (int idx = tid; idx < KC * 8 * NCOL; idx += NTHREADS) {
        int k = idx >> 6, c = idx & 63;
        int gate = c >> 4, lj = c & 15;
        sW2[k * SWSTR + c] = W_h[(size_t)k * G4H + gate * HID + j0 + lj];
    }
    if (tid < JPC * BPC) sC[tid] = 0.0f;
    __syncthreads();

    const int w    = tid >> 5;            // warp = k-chunk
    const int lane = tid & 31;
    const int hw   = lane >> 4;           // batch half: b in [4hw, 4hw+4)
    const int lc   = lane & 15;           // owns cols 4lc..4lc+3
    const int k0   = w * KC;
    const int c0   = 4 * lc;

    unsigned long long wreg[2][KC];       // [pair][k]
    {
        const uint32_t wb = smem_u32(sW2 + k0 * SWSTR + c0);
        #pragma unroll
        for (int k = 0; k < KC; k++) {
            asm volatile("ld.shared.u64 %0, [%1];"
                         : "=l"(wreg[0][k]) : "r"(wb + k * (SWSTR * 4)));
            asm volatile("ld.shared.u64 %0, [%1];"
                         : "=l"(wreg[1][k]) : "r"(wb + k * (SWSTR * 4) + 8));
        }
    }
    __syncthreads();   // sW2 dead after this

    const uint32_t hbase   = smem_u32(sH + k0 * BPC + 4 * hw);
    const uint32_t hstore  = smem_u32(sH + k0 * BPC) + lane * 16;
    unsigned* fA = &g_flags[bg][2 * w][0];
    unsigned* fB = &g_flags[bg][2 * w + 1][0];
    unsigned* myflag = &g_flags[bg][cg][0];

    const int lj = tid >> 3;              // epilogue decode (tid<128)
    const int bb = tid & 7;

    for (int s = 0; s < TSTEPS; s++) {
        const int rbuf = s & 1;
        float* sP = sPart + rbuf * (8 * BPC * PSTR);

        // ---- prefetch x_proj gate biases for epilogue (tid<128)
        float xr[4];
        if (tid < JPC * BPC) {
            const float* xpb = g_xp + ((size_t)((s * 16 + cg) * 8 + bg)) * 512
                             + bb * 64 + lj;
            #pragma unroll
            for (int gate = 0; gate < 4; gate++)
                xr[gate] = __ldg(xpb + gate * 16);
        }

        // ---- per-warp wait on my two producers
        if (s > 0) {
            if (lane < 2) {
                unsigned* f = lane ? fB : fA;
                unsigned v;
                do {
                    asm volatile("ld.acquire.gpu.global.u32 %0, [%1];"
                                 : "=r"(v) : "l"(f) : "memory");
                } while (v < (unsigned)s);
            }
            __syncwarp();
        }

        // ---- pull 1KB (two 512B blocks, layout matches sH directly)
        {
            const float4* src = reinterpret_cast<const float4*>(
                g_h[rbuf][bg][2 * w]);     // blocks 2w,2w+1 contiguous
            float4 v0 = __ldcg(src + lane);
            float4 v1 = __ldcg(src + 32 + lane);
            asm volatile("st.shared.v4.f32 [%0], {%1,%2,%3,%4};"
                         :: "r"(hstore), "f"(v0.x), "f"(v0.y), "f"(v0.z), "f"(v0.w));
            asm volatile("st.shared.v4.f32 [%0], {%1,%2,%3,%4};"
                         :: "r"(hstore + 512), "f"(v1.x), "f"(v1.y), "f"(v1.z), "f"(v1.w));
        }
        __syncwarp();

        // ---- GEMM: per k: 1 broadcast LDS.128 + 4 splats + 8 FMA2
        unsigned long long acc[2][4];
        #pragma unroll
        for (int p = 0; p < 2; p++)
            #pragma unroll
            for (int i = 0; i < 4; i++) acc[p][i] = 0ull;

        #pragma unroll
        for (int k = 0; k < KC; k++) {
            float h0, h1, h2f, h3;
            asm volatile("ld.shared.v4.f32 {%0,%1,%2,%3}, [%4];"
                         : "=f"(h0), "=f"(h1), "=f"(h2f), "=f"(h3)
                         : "r"(hbase + k * 32));
            unsigned long long hh[4];
            asm("mov.b64 %0, {%1, %1};" : "=l"(hh[0]) : "f"(h0));
            asm("mov.b64 %0, {%1, %1};" : "=l"(hh[1]) : "f"(h1));
            asm("mov.b64 %0, {%1, %1};" : "=l"(hh[2]) : "f"(h2f));
            asm("mov.b64 %0, {%1, %1};" : "=l"(hh[3]) : "f"(h3));
            #pragma unroll
            for (int i = 0; i < 4; i++) {
                asm volatile("fma.rn.f32x2 %0, %1, %2, %0;"
                             : "+l"(acc[0][i]) : "l"(hh[i]), "l"(wreg[0][k]));
                asm volatile("fma.rn.f32x2 %0, %1, %2, %0;"
                             : "+l"(acc[1][i]) : "l"(hh[i]), "l"(wreg[1][k]));
            }
        }

        // ---- write partials (u64 stores, no horizontal add needed)
        #pragma unroll
        for (int i = 0; i < 4; i++) {
            int row = (w * BPC + 4 * hw + i) * PSTR;
            *reinterpret_cast<unsigned long long*>(sP + row + c0)     = acc[0][i];
            *reinterpret_cast<unsigned long long*>(sP + row + c0 + 2) = acc[1][i];
        }
        __syncthreads();

        // ---- epilogue (warps 0-3): reduce 8 partials, activations, publish
        if (tid < JPC * BPC) {
            float g4[4];
            #pragma unroll
            for (int gate = 0; gate < 4; gate++) {
                int c = gate * JPC + lj;
                float v = xr[gate];
                #pragma unroll
                for (int q = 0; q < 8; q++)
                    v += sP[(q * BPC + bb) * PSTR + c];
                g4[gate] = v;
            }
            float ig = fast_sig(g4[0]);
            float fg = fast_sig(g4[1]);
            float gg = fast_tanh(g4[2]);
            float og = fast_sig(g4[3]);
            float cnew = fg * sC[tid] + ig * gg;
            sC[tid] = cnew;
            float hnew = og * fast_tanh(cnew);
            __stcg(&g_h[rbuf ^ 1][bg][cg][tid], hnew);   // 512B coalesced

            asm volatile("bar.sync 1, 128;" ::: "memory");
            if (tid == 0)
                asm volatile("st.release.gpu.global.u32 [%0], %1;"
                             :: "l"(myflag), "r"((unsigned)(s + 1)) : "memory");
        }
    }
}

// ---------------------------------------------------------------------------
// final FC: out[b][d] = sum_k h_final[k][b] * fc_w[k][d] + fc_b[d]
// ---------------------------------------------------------------------------
__global__ void fc_kernel(const float* __restrict__ fc_w,
                          const float* __restrict__ fc_b,
                          float* __restrict__ out) {
    int b = blockIdx.x;
    int d = threadIdx.x;
    int bg = b >> 3, bb = b & 7;
    float acc = fc_b[d];
    #pragma unroll 8
    for (int k = 0; k < HID; k++)
        acc += g_h[0][bg][k >> 4][(k & 15) * 8 + bb] * fc_w[k * DOUT + d];
    out[b * DOUT + d] = acc;
}

// ---------------------------------------------------------------------------
extern "C" void kernel_launch(void* const* d_in, const int* in_sizes, int n_in,
                              void* d_out, int out_size) {
    const float* x    = (const float*)d_in[0];
    const float* W_x  = (const float*)d_in[1];
    const float* W_h  = (const float*)d_in[2];
    const float* bvec = (const float*)d_in[3];
    const float* fc_w = (const float*)d_in[4];
    const float* fc_b = (const float*)d_in[5];
    float* out = (float*)d_out;

    cudaFuncSetAttribute(xproj_kernel,
                         cudaFuncAttributeMaxDynamicSharedMemorySize, XPK_BYTES);
    cudaFuncSetAttribute(lstm_scan_kernel,
                         cudaFuncAttributeMaxDynamicSharedMemorySize, SMEM_BYTES);

    init_kernel<<<(8 * 16 * 128 + 255) / 256, 256>>>();
    xproj_kernel<<<dim3(TSTEPS / 16, 8), NTHREADS, XPK_BYTES>>>(x, W_x, bvec);
    lstm_scan_kernel<<<NCTA, NTHREADS, SMEM_BYTES>>>(W_h);
    fc_kernel<<<BATCH, DOUT>>>(fc_w, fc_b, out);
}

// round 7
// speedup vs baseline: 1.3729x; 1.0046x over previous
#include <cuda_runtime.h>
#include <cuda_bf16.h>
#include <cstdint>

// Problem constants
#define BATCH 64
#define TSTEPS 2048
#define DIN 128
#define HID 256
#define DOUT 128
#define G4H (4*HID)        // 1024

// Scan tiling: 16 column-groups x 8 batch-groups = 128 CTAs
#define NCTA 128
#define CLUSTER 16
#define JPC 16             // hidden units per CTA
#define NCOL 64            // gate columns per CTA
#define BPC 8              // batches per CTA
#define KC 32              // K per warp (8 warps)
#define NTHREADS 256

// ---- shared SMEM pieces (both scan variants)
#define SWSTR 66                         // sW2 [k][c] staging stride
#define PSTR 70                          // sPart row stride

// cluster-kernel layout (floats)
#define CK_SW2   0                       // 256*66 = 16896 (setup only)
#define CK_HB    (CK_SW2 + 256*SWSTR)    // 2 x 2048  (mailbox [buf][k][b])
#define CK_PART  (CK_HB + 2*2048)        // 2 x 8 x 8 x PSTR
#define CK_C     (CK_PART + 2*8*8*PSTR)  // 128
#define CK_MB    (CK_C + 128)            // 32 mbarriers x 8B = 64 floats
#define CK_FLOATS (CK_MB + 64)
#define CK_SMEM_BYTES (CK_FLOATS*4)      // ~118 KB

// flags-kernel layout (floats) — identical to R6
#define FK_SW2   0
#define FK_H     (FK_SW2 + 256*SWSTR)    // sH [k(256)][b(8)] = 2048
#define FK_PART  (FK_H + 256*8)
#define FK_C     (FK_PART + 2*8*8*PSTR)
#define FK_FLOATS (FK_C + 128)
#define FK_SMEM_BYTES (FK_FLOATS*4)

// x_proj kernel smem
#define XP_XSTRIDE 133
#define XP_WSTRIDE 132
#define XPK_SX    0
#define XPK_SW    (128*XP_XSTRIDE)
#define XPK_FLOATS (XPK_SW + 128*XP_WSTRIDE)
#define XPK_BYTES (XPK_FLOATS*4)

// Global scratch
__device__ __align__(16) float g_xp[(size_t)TSTEPS * 16 * 8 * 512]; // [t][cg][bg][bb*64+c]
__device__ __align__(16) float g_h[2][8][16][JPC*BPC];              // [buf][bg][cg][lj*8+bb]
__device__ unsigned g_flags[8][16][32];                             // fallback path

__device__ __forceinline__ uint32_t smem_u32(const void* p) {
    return (uint32_t)__cvta_generic_to_shared(p);
}
__device__ __forceinline__ uint32_t mapa_u32(uint32_t addr, uint32_t rank) {
    uint32_t r;
    asm("mapa.shared::cluster.u32 %0, %1, %2;" : "=r"(r) : "r"(addr), "r"(rank));
    return r;
}
__device__ __forceinline__ float fast_sig(float x) {
    return __fdividef(1.0f, 1.0f + __expf(-x));
}
__device__ __forceinline__ float fast_tanh(float x) {
    return __fdividef(2.0f, 1.0f + __expf(-2.0f * x)) - 1.0f;
}
__device__ __forceinline__ void mb_wait_parity(uint32_t mb, uint32_t parity) {
    uint32_t done;
    asm volatile(
        "{\n\t.reg .pred p;\n\t"
        "mbarrier.try_wait.parity.shared::cta.b64 p, [%1], %2;\n\t"
        "selp.b32 %0, 1, 0, p;\n\t}"
        : "=r"(done) : "r"(mb), "r"(parity) : "memory");
    while (!done) {
        asm volatile(
            "{\n\t.reg .pred p;\n\t"
            "mbarrier.try_wait.parity.shared::cta.b64 p, [%1], %2, 0x989680;\n\t"
            "selp.b32 %0, 1, 0, p;\n\t}"
            : "=r"(done) : "r"(mb), "r"(parity) : "memory");
    }
}

// ---------------------------------------------------------------------------
__global__ void init_kernel() {
    int i = blockIdx.x * blockDim.x + threadIdx.x;
    if (i < 8 * 16 * 32) ((unsigned*)g_flags)[i] = 0u;
    if (i < 8 * 16 * JPC * BPC) ((float*)g_h[0])[i] = 0.0f;
}

// ---------------------------------------------------------------------------
// x_proj: g_xp[t][cg][bg][bb*64 + gate*16+lj] = x[b,t,:] . W_x[:, gcol] + bias
// ---------------------------------------------------------------------------
__global__ void __launch_bounds__(NTHREADS, 1)
xproj_kernel(const float* __restrict__ x,
             const float* __restrict__ W_x,
             const float* __restrict__ bias) {
    extern __shared__ float smem[];
    float* sX = smem + XPK_SX;
    float* sW = smem + XPK_SW;

    const int tid  = threadIdx.x;
    const int tblk = blockIdx.x;
    const int bg   = blockIdx.y;

    for (int idx = tid; idx < 128 * 32; idx += NTHREADS) {
        int r = idx >> 5, f4 = idx & 31;
        int tt = r >> 3, bb = r & 7;
        int b = bg * 8 + bb, t = tblk * 16 + tt;
        float4 v = __ldg(reinterpret_cast<const float4*>(
            x + ((size_t)b * TSTEPS + t) * DIN) + f4);
        float* dst = sX + r * XP_XSTRIDE + f4 * 4;
        dst[0] = v.x; dst[1] = v.y; dst[2] = v.z; dst[3] = v.w;
    }

    const int cq = tid & 7;
    const int rg = tid >> 3;

    for (int p = 0; p < 8; p++) {
        const int cp0 = p * 128;
        __syncthreads();
        for (int idx = tid; idx < 128 * 32; idx += NTHREADS) {
            int d = idx >> 5, c4 = idx & 31;
            float4 v = __ldg(reinterpret_cast<const float4*>(
                W_x + (size_t)d * G4H + cp0) + c4);
            float* dst = sW + d * XP_WSTRIDE + c4 * 4;
            dst[0] = v.x; dst[1] = v.y; dst[2] = v.z; dst[3] = v.w;
        }
        __syncthreads();

        unsigned long long acc[4][8];
        #pragma unroll
        for (int qq = 0; qq < 8; qq++) {
            float2 bv = __ldg(reinterpret_cast<const float2*>(
                bias + cp0 + 2 * (cq + 8 * qq)));
            unsigned long long bu;
            asm("mov.b64 %0, {%1, %2};" : "=l"(bu) : "f"(bv.x), "f"(bv.y));
            #pragma unroll
            for (int rr = 0; rr < 4; rr++) acc[rr][qq] = bu;
        }

        #pragma unroll 4
        for (int d = 0; d < 128; d++) {
            unsigned long long x2[4];
            #pragma unroll
            for (int rr = 0; rr < 4; rr++) {
                float xv = sX[(rg * 4 + rr) * XP_XSTRIDE + d];
                asm("mov.b64 %0, {%1, %1};" : "=l"(x2[rr]) : "f"(xv));
            }
            const uint32_t wrow = smem_u32(sW + d * XP_WSTRIDE + 2 * cq);
            #pragma unroll
            for (int qq = 0; qq < 8; qq++) {
                unsigned long long w2;
                asm volatile("ld.shared.u64 %0, [%1];"
                             : "=l"(w2) : "r"(wrow + qq * 64));
                #pragma unroll
                for (int rr = 0; rr < 4; rr++)
                    asm volatile("fma.rn.f32x2 %0, %1, %2, %0;"
                                 : "+l"(acc[rr][qq]) : "l"(x2[rr]), "l"(w2));
            }
        }

        #pragma unroll
        for (int rr = 0; rr < 4; rr++) {
            int r = rg * 4 + rr;
            int tt = r >> 3, bb = r & 7;
            int t = tblk * 16 + tt;
            #pragma unroll
            for (int qq = 0; qq < 8; qq++) {
                int cglob = cp0 + 2 * (cq + 8 * qq);
                int gate = cglob >> 8, rem = cglob & 255;
                int cg = rem >> 4, lj = rem & 15;
                float lo, hi;
                asm("mov.b64 {%0,%1}, %2;" : "=f"(lo), "=f"(hi) : "l"(acc[rr][qq]));
                float2* dst = reinterpret_cast<float2*>(
                    g_xp + ((size_t)((t * 16 + cg) * 8 + bg)) * 512
                         + bb * 64 + gate * 16 + lj);
                *dst = make_float2(lo, hi);
            }
        }
    }
}

// ---------------------------------------------------------------------------
// CLUSTER scan: W in registers, DSMEM mailbox push, per-producer mbarriers
// ---------------------------------------------------------------------------
__global__ void __launch_bounds__(NTHREADS, 1)
lstm_scan_cluster(const float* __restrict__ W_h) {
    extern __shared__ float smem[];
    float* sW2   = smem + CK_SW2;   // staging (setup only)
    float* sHB   = smem + CK_HB;    // [buf][k(256)][b(8)]
    float* sPart = smem + CK_PART;  // [buf][w][b][c] stride PSTR
    float* sC    = smem + CK_C;

    const int tid = threadIdx.x;
    uint32_t cgu;
    asm("mov.u32 %0, %%cluster_ctarank;" : "=r"(cgu));
    const int cg = (int)cgu;
    const int bg = blockIdx.x >> 4;
    const int j0 = cg * JPC;

    const uint32_t mb_base = smem_u32(smem + CK_MB);   // mbs[buf][16], 8B each

    // init mbarriers (count 1 each) + zero mailbox buf0
    if (tid < 32)
        asm volatile("mbarrier.init.shared.b64 [%0], %1;"
                     :: "r"(mb_base + tid * 8), "r"(1) : "memory");
    for (int i = tid; i < 2048; i += NTHREADS) sHB[i] = 0.0f;

    // stage W_h slice as [k][c]
    for (int idx = tid; idx < KC * 8 * NCOL; idx += NTHREADS) {
        int k = idx >> 6, c = idx & 63;
        int gate = c >> 4, lj = c & 15;
        sW2[k * SWSTR + c] = W_h[(size_t)k * G4H + gate * HID + j0 + lj];
    }
    if (tid < JPC * BPC) sC[tid] = 0.0f;
    __syncthreads();

    const int w    = tid >> 5;
    const int lane = tid & 31;
    const int hw   = lane >> 4;
    const int lc   = lane & 15;
    const int k0   = w * KC;
    const int c0   = 4 * lc;

    unsigned long long wreg[2][KC];
    {
        const uint32_t wb = smem_u32(sW2 + k0 * SWSTR + c0);
        #pragma unroll
        for (int k = 0; k < KC; k++) {
            asm volatile("ld.shared.u64 %0, [%1];"
                         : "=l"(wreg[0][k]) : "r"(wb + k * (SWSTR * 4)));
            asm volatile("ld.shared.u64 %0, [%1];"
                         : "=l"(wreg[1][k]) : "r"(wb + k * (SWSTR * 4) + 8));
        }
    }
    __syncthreads();   // sW2 dead; all mbarriers + mailbox initialized

    // cluster-wide handshake ONCE (mb init visible before any remote arrive)
    asm volatile("barrier.cluster.arrive.aligned;" ::: "memory");
    asm volatile("barrier.cluster.wait.aligned;" ::: "memory");

    const uint32_t hb0 = smem_u32(sHB) + k0 * 32 + hw * 16;   // [k][b] rows
    const uint32_t mbA = mb_base + (2 * w) * 8;               // + buf*128
    const uint32_t mbB = mb_base + (2 * w + 1) * 8;
    const uint32_t hb_local = smem_u32(sHB);

    const int lj = tid >> 3;   // epilogue decode (tid<128)
    const int bb = tid & 7;

    int ph0 = 0, ph1 = 0;      // wait parity per buffer
    float hlast = 0.0f;

    for (int s = 0; s < TSTEPS; s++) {
        const int buf = s & 1;
        float* sP = sPart + buf * (8 * BPC * PSTR);

        // ---- prefetch x_proj gate biases (tid<128)
        float xr[4];
        if (tid < JPC * BPC) {
            const float* xpb = g_xp + ((size_t)((s * 16 + cg) * 8 + bg)) * 512
                             + bb * 64 + lj;
            #pragma unroll
            for (int gate = 0; gate < 4; gate++)
                xr[gate] = __ldg(xpb + gate * 16);
        }

        // ---- wait my two producers (HW sleep, no polling)
        if (s > 0) {
            int par = buf ? ph1 : ph0;
            mb_wait_parity(mbA + buf * 128, (uint32_t)par);
            mb_wait_parity(mbB + buf * 128, (uint32_t)par);
            if (buf) ph1 ^= 1; else ph0 ^= 1;
            asm volatile("fence.acq_rel.cluster;" ::: "memory");
        }

        // ---- GEMM straight out of the local mailbox
        unsigned long long acc[2][4];
        #pragma unroll
        for (int p = 0; p < 2; p++)
            #pragma unroll
            for (int i = 0; i < 4; i++) acc[p][i] = 0ull;

        const uint32_t hbase = hb0 + buf * 8192;
        #pragma unroll
        for (int k = 0; k < KC; k++) {
            float h0, h1, h2f, h3;
            asm volatile("ld.shared.v4.f32 {%0,%1,%2,%3}, [%4];"
                         : "=f"(h0), "=f"(h1), "=f"(h2f), "=f"(h3)
                         : "r"(hbase + k * 32));
            unsigned long long hh[4];
            asm("mov.b64 %0, {%1, %1};" : "=l"(hh[0]) : "f"(h0));
            asm("mov.b64 %0, {%1, %1};" : "=l"(hh[1]) : "f"(h1));
            asm("mov.b64 %0, {%1, %1};" : "=l"(hh[2]) : "f"(h2f));
            asm("mov.b64 %0, {%1, %1};" : "=l"(hh[3]) : "f"(h3));
            #pragma unroll
            for (int i = 0; i < 4; i++) {
                asm volatile("fma.rn.f32x2 %0, %1, %2, %0;"
                             : "+l"(acc[0][i]) : "l"(hh[i]), "l"(wreg[0][k]));
                asm volatile("fma.rn.f32x2 %0, %1, %2, %0;"
                             : "+l"(acc[1][i]) : "l"(hh[i]), "l"(wreg[1][k]));
            }
        }

        #pragma unroll
        for (int i = 0; i < 4; i++) {
            int row = (w * BPC + 4 * hw + i) * PSTR;
            *reinterpret_cast<unsigned long long*>(sP + row + c0)     = acc[0][i];
            *reinterpret_cast<unsigned long long*>(sP + row + c0 + 2) = acc[1][i];
        }
        __syncthreads();

        // ---- epilogue (warps 0-3): reduce, activations, DSMEM push, arrive
        if (tid < JPC * BPC) {
            float g4[4];
            #pragma unroll
            for (int gate = 0; gate < 4; gate++) {
                int c = gate * JPC + lj;
                float v = xr[gate];
                #pragma unroll
                for (int q = 0; q < 8; q++)
                    v += sP[(q * BPC + bb) * PSTR + c];
                g4[gate] = v;
            }
            float ig = fast_sig(g4[0]);
            float fg = fast_sig(g4[1]);
            float gg = fast_tanh(g4[2]);
            float og = fast_sig(g4[3]);
            float cnew = fg * sC[tid] + ig * gg;
            sC[tid] = cnew;
            float hnew = og * fast_tanh(cnew);
            hlast = hnew;

            // push my element into all 16 peers' mailbox buf (s+1)&1
            const int nbuf = (s + 1) & 1;
            const uint32_t dstoff = hb_local + (nbuf * 2048 + cg * 128 + tid) * 4;
            #pragma unroll
            for (int p = 0; p < CLUSTER; p++) {
                uint32_t a = mapa_u32(dstoff, (uint32_t)p);
                asm volatile("st.shared::cluster.f32 [%0], %1;"
                             :: "r"(a), "f"(hnew) : "memory");
            }
            asm volatile("bar.sync 1, 128;" ::: "memory");
            if (tid == 0) {
                asm volatile("fence.acq_rel.cluster;" ::: "memory");
                const uint32_t mymb = mb_base + (nbuf * 16 + cg) * 8;
                #pragma unroll
                for (int p = 0; p < CLUSTER; p++) {
                    uint32_t a = mapa_u32(mymb, (uint32_t)p);
                    asm volatile(
                        "mbarrier.arrive.release.cluster.shared::cluster.b64 _, [%0];"
                        :: "r"(a) : "memory");
                }
            }
        }
    }

    // publish final h for fc
    if (tid < JPC * BPC)
        g_h[0][bg][cg][tid] = hlast;

    // keep cluster alive until everyone is done touching peer SMEM
    asm volatile("barrier.cluster.arrive.aligned;" ::: "memory");
    asm volatile("barrier.cluster.wait.aligned;" ::: "memory");
}

// ---------------------------------------------------------------------------
// FALLBACK scan (R6, proven): W in registers, global flag sync
// ---------------------------------------------------------------------------
__global__ void __launch_bounds__(NTHREADS, 1)
lstm_scan_flags(const float* __restrict__ W_h) {
    extern __shared__ float smem[];
    float* sW2   = smem + FK_SW2;
    float* sH    = smem + FK_H;
    float* sPart = smem + FK_PART;
    float* sC    = smem + FK_C;

    const int tid = threadIdx.x;
    const int cg  = blockIdx.x & 15;
    const int bg  = blockIdx.x >> 4;
    const int j0  = cg * JPC;

    for (int idx = tid; idx < KC * 8 * NCOL; idx += NTHREADS) {
        int k = idx >> 6, c = idx & 63;
        int gate = c >> 4, lj = c & 15;
        sW2[k * SWSTR + c] = W_h[(size_t)k * G4H + gate * HID + j0 + lj];
    }
    if (tid < JPC * BPC) sC[tid] = 0.0f;
    __syncthreads();

    const int w    = tid >> 5;
    const int lane = tid & 31;
    const int hw   = lane >> 4;
    const int lc   = lane & 15;
    const int k0   = w * KC;
    const int c0   = 4 * lc;

    unsigned long long wreg[2][KC];
    {
        const uint32_t wb = smem_u32(sW2 + k0 * SWSTR + c0);
        #pragma unroll
        for (int k = 0; k < KC; k++) {
            asm volatile("ld.shared.u64 %0, [%1];"
                         : "=l"(wreg[0][k]) : "r"(wb + k * (SWSTR * 4)));
            asm volatile("ld.shared.u64 %0, [%1];"
                         : "=l"(wreg[1][k]) : "r"(wb + k * (SWSTR * 4) + 8));
        }
    }
    __syncthreads();

    const uint32_t hbase  = smem_u32(sH + k0 * BPC + 4 * hw);
    const uint32_t hstore = smem_u32(sH + k0 * BPC) + lane * 16;
    unsigned* fA = &g_flags[bg][2 * w][0];
    unsigned* fB = &g_flags[bg][2 * w + 1][0];
    unsigned* myflag = &g_flags[bg][cg][0];

    const int lj = tid >> 3;
    const int bb = tid & 7;

    for (int s = 0; s < TSTEPS; s++) {
        const int rbuf = s & 1;
        float* sP = sPart + rbuf * (8 * BPC * PSTR);

        float xr[4];
        if (tid < JPC * BPC) {
            const float* xpb = g_xp + ((size_t)((s * 16 + cg) * 8 + bg)) * 512
                             + bb * 64 + lj;
            #pragma unroll
            for (int gate = 0; gate < 4; gate++)
                xr[gate] = __ldg(xpb + gate * 16);
        }

        if (s > 0) {
            if (lane < 2) {
                unsigned* f = lane ? fB : fA;
                unsigned v;
                do {
                    asm volatile("ld.acquire.gpu.global.u32 %0, [%1];"
                                 : "=r"(v) : "l"(f) : "memory");
                } while (v < (unsigned)s);
            }
            __syncwarp();
        }
        {
            const float4* src = reinterpret_cast<const float4*>(
                g_h[rbuf][bg][2 * w]);
            float4 v0 = __ldcg(src + lane);
            float4 v1 = __ldcg(src + 32 + lane);
            asm volatile("st.shared.v4.f32 [%0], {%1,%2,%3,%4};"
                         :: "r"(hstore), "f"(v0.x), "f"(v0.y), "f"(v0.z), "f"(v0.w));
            asm volatile("st.shared.v4.f32 [%0], {%1,%2,%3,%4};"
                         :: "r"(hstore + 512), "f"(v1.x), "f"(v1.y), "f"(v1.z), "f"(v1.w));
        }
        __syncwarp();

        unsigned long long acc[2][4];
        #pragma unroll
        for (int p = 0; p < 2; p++)
            #pragma unroll
            for (int i = 0; i < 4; i++) acc[p][i] = 0ull;

        #pragma unroll
        for (int k = 0; k < KC; k++) {
            float h0, h1, h2f, h3;
            asm volatile("ld.shared.v4.f32 {%0,%1,%2,%3}, [%4];"
                         : "=f"(h0), "=f"(h1), "=f"(h2f), "=f"(h3)
                         : "r"(hbase + k * 32));
            unsigned long long hh[4];
            asm("mov.b64 %0, {%1, %1};" : "=l"(hh[0]) : "f"(h0));
            asm("mov.b64 %0, {%1, %1};" : "=l"(hh[1]) : "f"(h1));
            asm("mov.b64 %0, {%1, %1};" : "=l"(hh[2]) : "f"(h2f));
            asm("mov.b64 %0, {%1, %1};" : "=l"(hh[3]) : "f"(h3));
            #pragma unroll
            for (int i = 0; i < 4; i++) {
                asm volatile("fma.rn.f32x2 %0, %1, %2, %0;"
                             : "+l"(acc[0][i]) : "l"(hh[i]), "l"(wreg[0][k]));
                asm volatile("fma.rn.f32x2 %0, %1, %2, %0;"
                             : "+l"(acc[1][i]) : "l"(hh[i]), "l"(wreg[1][k]));
            }
        }

        #pragma unroll
        for (int i = 0; i < 4; i++) {
            int row = (w * BPC + 4 * hw + i) * PSTR;
            *reinterpret_cast<unsigned long long*>(sP + row + c0)     = acc[0][i];
            *reinterpret_cast<unsigned long long*>(sP + row + c0 + 2) = acc[1][i];
        }
        __syncthreads();

        if (tid < JPC * BPC) {
            float g4[4];
            #pragma unroll
            for (int gate = 0; gate < 4; gate++) {
                int c = gate * JPC + lj;
                float v = xr[gate];
                #pragma unroll
                for (int q = 0; q < 8; q++)
                    v += sP[(q * BPC + bb) * PSTR + c];
                g4[gate] = v;
            }
            float ig = fast_sig(g4[0]);
            float fg = fast_sig(g4[1]);
            float gg = fast_tanh(g4[2]);
            float og = fast_sig(g4[3]);
            float cnew = fg * sC[tid] + ig * gg;
            sC[tid] = cnew;
            float hnew = og * fast_tanh(cnew);
            __stcg(&g_h[rbuf ^ 1][bg][cg][tid], hnew);

            asm volatile("bar.sync 1, 128;" ::: "memory");
            if (tid == 0)
                asm volatile("st.release.gpu.global.u32 [%0], %1;"
                             :: "l"(myflag), "r"((unsigned)(s + 1)) : "memory");
        }
    }
}

// ---------------------------------------------------------------------------
__global__ void fc_kernel(const float* __restrict__ fc_w,
                          const float* __restrict__ fc_b,
                          float* __restrict__ out) {
    int b = blockIdx.x;
    int d = threadIdx.x;
    int bg = b >> 3, bb = b & 7;
    float acc = fc_b[d];
    #pragma unroll 8
    for (int k = 0; k < HID; k++)
        acc += g_h[0][bg][k >> 4][(k & 15) * 8 + bb] * fc_w[k * DOUT + d];
    out[b * DOUT + d] = acc;
}

// ---------------------------------------------------------------------------
extern "C" void kernel_launch(void* const* d_in, const int* in_sizes, int n_in,
                              void* d_out, int out_size) {
    const float* x    = (const float*)d_in[0];
    const float* W_x  = (const float*)d_in[1];
    const float* W_h  = (const float*)d_in[2];
    const float* bvec = (const float*)d_in[3];
    const float* fc_w = (const float*)d_in[4];
    const float* fc_b = (const float*)d_in[5];
    float* out = (float*)d_out;

    cudaFuncSetAttribute(xproj_kernel,
                         cudaFuncAttributeMaxDynamicSharedMemorySize, XPK_BYTES);
    cudaFuncSetAttribute(lstm_scan_flags,
                         cudaFuncAttributeMaxDynamicSharedMemorySize, FK_SMEM_BYTES);

    init_kernel<<<(8 * 16 * 128 + 255) / 256, 256>>>();
    xproj_kernel<<<dim3(TSTEPS / 16, 8), NTHREADS, XPK_BYTES>>>(x, W_x, bvec);

    bool cluster_ok = false;
    do {
        if (cudaFuncSetAttribute(lstm_scan_cluster,
                cudaFuncAttributeMaxDynamicSharedMemorySize, CK_SMEM_BYTES)
            != cudaSuccess) break;
        if (cudaFuncSetAttribute(lstm_scan_cluster,
                cudaFuncAttributeNonPortableClusterSizeAllowed, 1)
            != cudaSuccess) break;

        cudaLaunchConfig_t cfg = {};
        cfg.gridDim = dim3(NCTA, 1, 1);
        cfg.blockDim = dim3(NTHREADS, 1, 1);
        cfg.dynamicSmemBytes = CK_SMEM_BYTES;
        cudaLaunchAttribute attrs[1];
        attrs[0].id = cudaLaunchAttributeClusterDimension;
        attrs[0].val.clusterDim = {CLUSTER, 1, 1};
        cfg.attrs = attrs;
        cfg.numAttrs = 1;

        int nclusters = 0;
        if (cudaOccupancyMaxActiveClusters(&nclusters, lstm_scan_cluster, &cfg)
            != cudaSuccess) break;
        if (nclusters < NCTA / CLUSTER) break;

        if (cudaLaunchKernelEx(&cfg, lstm_scan_cluster, W_h) != cudaSuccess)
            break;
        cluster_ok = true;
    } while (0);

    if (!cluster_ok) {
        cudaGetLastError();
        lstm_scan_flags<<<NCTA, NTHREADS, FK_SMEM_BYTES>>>(W_h);
    }

    fc_kernel<<<BATCH, DOUT>>>(fc_w, fc_b, out);
}